// round 8
// baseline (speedup 1.0000x reference)
#include <cuda_runtime.h>
#include <cstdint>

#define Nn 100000
#define Ee 1600000
#define Hh 8
#define HC 128   // H*C == DIM
#define NB 391   // ceil(Nn/256)

// ---- scratch (device globals; no allocation allowed) ----
__device__ float g_q[(size_t)Nn * HC];
__device__ float g_kv[(size_t)Nn * 256];     // k | v interleaved per node
__device__ float g_biasS[(size_t)Ee * Hh];   // edge bias, sorted by dst
__device__ int   g_cnt[Nn];
__device__ int   g_off[Nn + 1];
__device__ int   g_pos[Nn];
__device__ int   g_bsum[512];
__device__ int   g_src[Ee];                  // src node, sorted by dst

// ---- host-side fork/join resources (created once; NOT device memory) ----
struct HxStreams {
    cudaStream_t s2;
    cudaEvent_t  fork, join;
    HxStreams() {
        cudaStreamCreateWithFlags(&s2, cudaStreamNonBlocking);
        cudaEventCreateWithFlags(&fork, cudaEventDisableTiming);
        cudaEventCreateWithFlags(&join, cudaEventDisableTiming);
    }
};
static HxStreams g_hx;

// ===========================================================================
// tf32 helpers (base PTX, works on compute_103)
// ===========================================================================
__device__ __forceinline__ float tf32_rna(float f) {
    uint32_t u;
    asm("cvt.rna.tf32.f32 %0, %1;" : "=r"(u) : "f"(f));
    return __uint_as_float(u);
}

__device__ __forceinline__ void mma8(float* d, const uint32_t* a,
                                     uint32_t b0, uint32_t b1) {
    asm volatile(
        "mma.sync.aligned.m16n8k8.row.col.f32.tf32.tf32.f32 "
        "{%0,%1,%2,%3}, {%4,%5,%6,%7}, {%8,%9}, {%0,%1,%2,%3};"
        : "+f"(d[0]), "+f"(d[1]), "+f"(d[2]), "+f"(d[3])
        : "r"(a[0]), "r"(a[1]), "r"(a[2]), "r"(a[3]), "r"(b0), "r"(b1));
}

// ===========================================================================
// projections via tensor cores (3xTF32): q/k/v = x @ W.T
// ===========================================================================
#define KC   32
#define PAD  36
#define SM_FLOATS (4 * 128 * PAD)

__global__ __launch_bounds__(256, 2) void k_projMMA(
    const float* __restrict__ x,
    const float* __restrict__ Wq,
    const float* __restrict__ Wk,
    const float* __restrict__ Wv)
{
    extern __shared__ float sm[];
    float* AsH = sm;
    float* AsL = AsH + 128 * PAD;
    float* BsH = AsL + 128 * PAD;
    float* BsL = BsH + 128 * PAD;

    const int tid   = threadIdx.x;
    const int wid   = tid >> 5;
    const int lane  = tid & 31;
    const int warpM = wid & 3;
    const int warpN = wid >> 2;
    const int gr    = lane >> 2;
    const int qt    = lane & 3;
    const int row0  = blockIdx.x * 128;

    const float* W  = (blockIdx.y == 0) ? Wq : (blockIdx.y == 1) ? Wk : Wv;
    float*  outp    = (blockIdx.y == 0) ? g_q : g_kv;
    const int ostr  = (blockIdx.y == 0) ? 128 : 256;
    const int ooff  = (blockIdx.y == 2) ? 128 : 0;

    float d[2][8][4];
#pragma unroll
    for (int mf = 0; mf < 2; mf++)
#pragma unroll
        for (int nf = 0; nf < 8; nf++)
#pragma unroll
            for (int i = 0; i < 4; i++) d[mf][nf][i] = 0.f;

#pragma unroll 1
    for (int kc = 0; kc < 128; kc += KC) {
#pragma unroll
        for (int it = 0; it < 4; it++) {
            int lin = tid + it * 256;
            int r   = lin >> 3;
            int c4  = (lin & 7) << 2;
            float4 v = make_float4(0.f, 0.f, 0.f, 0.f);
            if (row0 + r < Nn)
                v = *(const float4*)(x + (size_t)(row0 + r) * 128 + kc + c4);
            float4 hi = make_float4(tf32_rna(v.x), tf32_rna(v.y), tf32_rna(v.z), tf32_rna(v.w));
            float4 lo = make_float4(tf32_rna(v.x - hi.x), tf32_rna(v.y - hi.y),
                                    tf32_rna(v.z - hi.z), tf32_rna(v.w - hi.w));
            *(float4*)(AsH + r * PAD + c4) = hi;
            *(float4*)(AsL + r * PAD + c4) = lo;

            float4 w = *(const float4*)(W + (size_t)r * 128 + kc + c4);
            float4 wh = make_float4(tf32_rna(w.x), tf32_rna(w.y), tf32_rna(w.z), tf32_rna(w.w));
            float4 wl = make_float4(tf32_rna(w.x - wh.x), tf32_rna(w.y - wh.y),
                                    tf32_rna(w.z - wh.z), tf32_rna(w.w - wh.w));
            *(float4*)(BsH + r * PAD + c4) = wh;
            *(float4*)(BsL + r * PAD + c4) = wl;
        }
        __syncthreads();

#pragma unroll
        for (int k0 = 0; k0 < KC; k0 += 8) {
            uint32_t aH[2][4], aL[2][4];
#pragma unroll
            for (int mf = 0; mf < 2; mf++) {
                const float* pH = AsH + (warpM * 32 + mf * 16 + gr) * PAD + k0 + qt;
                const float* pL = AsL + (warpM * 32 + mf * 16 + gr) * PAD + k0 + qt;
                aH[mf][0] = __float_as_uint(pH[0]);
                aH[mf][1] = __float_as_uint(pH[8 * PAD]);
                aH[mf][2] = __float_as_uint(pH[4]);
                aH[mf][3] = __float_as_uint(pH[8 * PAD + 4]);
                aL[mf][0] = __float_as_uint(pL[0]);
                aL[mf][1] = __float_as_uint(pL[8 * PAD]);
                aL[mf][2] = __float_as_uint(pL[4]);
                aL[mf][3] = __float_as_uint(pL[8 * PAD + 4]);
            }
#pragma unroll
            for (int nf = 0; nf < 8; nf++) {
                const float* pBH = BsH + (warpN * 64 + nf * 8 + gr) * PAD + k0 + qt;
                const float* pBL = BsL + (warpN * 64 + nf * 8 + gr) * PAD + k0 + qt;
                uint32_t bh0 = __float_as_uint(pBH[0]);
                uint32_t bh1 = __float_as_uint(pBH[4]);
                uint32_t bl0 = __float_as_uint(pBL[0]);
                uint32_t bl1 = __float_as_uint(pBL[4]);
                mma8(d[0][nf], aH[0], bh0, bh1);
                mma8(d[1][nf], aH[1], bh0, bh1);
                mma8(d[0][nf], aH[0], bl0, bl1);
                mma8(d[1][nf], aH[1], bl0, bl1);
                mma8(d[0][nf], aL[0], bh0, bh1);
                mma8(d[1][nf], aL[1], bh0, bh1);
            }
        }
        __syncthreads();
    }

#pragma unroll
    for (int mf = 0; mf < 2; mf++) {
        int r = row0 + warpM * 32 + mf * 16 + gr;
#pragma unroll
        for (int nf = 0; nf < 8; nf++) {
            int c = warpN * 64 + nf * 8 + qt * 2 + ooff;
            if (r < Nn)
                *(float2*)(outp + (size_t)r * ostr + c) = make_float2(d[mf][nf][0], d[mf][nf][1]);
            if (r + 8 < Nn)
                *(float2*)(outp + (size_t)(r + 8) * ostr + c) = make_float2(d[mf][nf][2], d[mf][nf][3]);
        }
    }
}

// ---------------------------------------------------------------------------
__global__ void k_zero() {
    int i = blockIdx.x * 256 + threadIdx.x;
    if (i < Nn) g_cnt[i] = 0;
}

// ---------------------------------------------------------------------------
// counting sort by dst: histogram -> scan -> scatter(+bias)
// ---------------------------------------------------------------------------
__global__ void k_hist(const int* __restrict__ ei) {
    int e = blockIdx.x * 256 + threadIdx.x;
    if (e < Ee) atomicAdd(&g_cnt[ei[Ee + e]], 1);
}

__global__ void k_scan1() {
    __shared__ int sh[256];
    int i = blockIdx.x * 256 + threadIdx.x;
    int v = (i < Nn) ? g_cnt[i] : 0;
    sh[threadIdx.x] = v;
    __syncthreads();
#pragma unroll
    for (int s = 128; s > 0; s >>= 1) {
        if (threadIdx.x < s) sh[threadIdx.x] += sh[threadIdx.x + s];
        __syncthreads();
    }
    if (threadIdx.x == 0) g_bsum[blockIdx.x] = sh[0];
}

__global__ void k_scan2() {
    __shared__ int sh[512];
    int t = threadIdx.x;
    sh[t] = (t < NB) ? g_bsum[t] : 0;
    __syncthreads();
#pragma unroll
    for (int s = 1; s < 512; s <<= 1) {
        int add = (t >= s) ? sh[t - s] : 0;
        __syncthreads();
        sh[t] += add;
        __syncthreads();
    }
    if (t < NB) g_bsum[t] = (t == 0) ? 0 : sh[t - 1];
    if (t == 0) g_off[Nn] = Ee;
}

__global__ void k_scan3() {
    __shared__ int sh[256];
    int i = blockIdx.x * 256 + threadIdx.x;
    int t = threadIdx.x;
    int v = (i < Nn) ? g_cnt[i] : 0;
    sh[t] = v;
    __syncthreads();
#pragma unroll
    for (int s = 1; s < 256; s <<= 1) {
        int add = (t >= s) ? sh[t - s] : 0;
        __syncthreads();
        sh[t] += add;
        __syncthreads();
    }
    if (i < Nn) {
        int off = g_bsum[blockIdx.x] + sh[t] - v;
        g_off[i] = off;
        g_pos[i] = off;
    }
}

// scatter + edge-bias precompute into sorted order
__global__ __launch_bounds__(256) void k_scatter(
    const int* __restrict__ ei,
    const float* __restrict__ eattr,
    const float* __restrict__ We)
{
    __shared__ float We_s[256];
    We_s[threadIdx.x] = We[threadIdx.x];
    __syncthreads();

    int e = blockIdx.x * 256 + threadIdx.x;
    if (e >= Ee) return;
    int src = ei[e];
    int dst = ei[Ee + e];
    int p = atomicAdd(&g_pos[dst], 1);
    g_src[p] = src;

    float4 a[8];
    const float4* ap = (const float4*)(eattr + (size_t)e * 32);
#pragma unroll
    for (int i = 0; i < 8; i++) a[i] = __ldg(ap + i);

    float b[8];
#pragma unroll
    for (int h = 0; h < 8; h++) {
        const float* w = We_s + h * 32;
        float s = 0.f;
#pragma unroll
        for (int i = 0; i < 8; i++) {
            s = fmaf(a[i].x, w[i * 4 + 0], s);
            s = fmaf(a[i].y, w[i * 4 + 1], s);
            s = fmaf(a[i].z, w[i * 4 + 2], s);
            s = fmaf(a[i].w, w[i * 4 + 3], s);
        }
        b[h] = s;
    }
    float* bp = g_biasS + (size_t)p * 8;
    *(float4*)(bp)     = make_float4(b[0], b[1], b[2], b[3]);
    *(float4*)(bp + 4) = make_float4(b[4], b[5], b[6], b[7]);
}

// ---------------------------------------------------------------------------
// fused edge pass: one warp per dst node, unroll x2 + src/bias prefetch
// pipeline (breaks the src->gather address dependency in steady state).
// ---------------------------------------------------------------------------
__global__ __launch_bounds__(256) void k_fused(float* __restrict__ out)
{
    const int warp = threadIdx.x >> 5;
    const int lane = threadIdx.x & 31;
    const int d = blockIdx.x * 8 + warp;
    if (d >= Nn) return;

    const int beg = g_off[d];
    const int end = g_off[d + 1];
    const int g = lane >> 2;

    const float4 q4 = __ldg((const float4*)(g_q + (size_t)d * 128 + lane * 4));

    float den = 0.f;
    float4 acc = make_float4(0.f, 0.f, 0.f, 0.f);

    // prologue: load first pair's src + bias
    int   s0 = 0, s1 = 0;
    float b0 = 0.f, b1 = 0.f;
    if (beg < end) {
        s0 = __ldg(g_src + beg);
        b0 = __ldg(g_biasS + (size_t)beg * 8 + g);
    }
    if (beg + 1 < end) {
        s1 = __ldg(g_src + beg + 1);
        b1 = __ldg(g_biasS + (size_t)(beg + 1) * 8 + g);
    }

    int p = beg;
#pragma unroll 1
    for (; p + 1 < end; p += 2) {
        // prefetch next pair's src + bias (clamped, values dropped on exit)
        const int np0 = (p + 2 < end) ? p + 2 : p;
        const int np1 = (p + 3 < end) ? p + 3 : p;
        const int   ns0 = __ldg(g_src + np0);
        const int   ns1 = __ldg(g_src + np1);
        const float nb0 = __ldg(g_biasS + (size_t)np0 * 8 + g);
        const float nb1 = __ldg(g_biasS + (size_t)np1 * 8 + g);

        // gathers for current pair (addresses already resolved)
        const float4 k0 = __ldg((const float4*)(g_kv + (size_t)s0 * 256 + lane * 4));
        const float4 k1 = __ldg((const float4*)(g_kv + (size_t)s1 * 256 + lane * 4));
        const float4 v0 = __ldg((const float4*)(g_kv + (size_t)s0 * 256 + 128 + lane * 4));
        const float4 v1 = __ldg((const float4*)(g_kv + (size_t)s1 * 256 + 128 + lane * 4));

        float t0 = (q4.x * k0.x + q4.y * k0.y + q4.z * k0.z + q4.w * k0.w) * 0.25f;
        float t1 = (q4.x * k1.x + q4.y * k1.y + q4.z * k1.z + q4.w * k1.w) * 0.25f;
        t0 += __shfl_xor_sync(0xffffffffu, t0, 1);
        t0 += __shfl_xor_sync(0xffffffffu, t0, 2);
        t1 += __shfl_xor_sync(0xffffffffu, t1, 1);
        t1 += __shfl_xor_sync(0xffffffffu, t1, 2);

        const float e0 = __expf(t0 + b0);
        const float e1 = __expf(t1 + b1);
        den += e0 + e1;
        acc.x = fmaf(e0, v0.x, fmaf(e1, v1.x, acc.x));
        acc.y = fmaf(e0, v0.y, fmaf(e1, v1.y, acc.y));
        acc.z = fmaf(e0, v0.z, fmaf(e1, v1.z, acc.z));
        acc.w = fmaf(e0, v0.w, fmaf(e1, v1.w, acc.w));

        s0 = ns0; s1 = ns1; b0 = nb0; b1 = nb1;
    }
    if (p < end) {   // tail edge (src/bias already in s0/b0)
        const float4 k0 = __ldg((const float4*)(g_kv + (size_t)s0 * 256 + lane * 4));
        const float4 v0 = __ldg((const float4*)(g_kv + (size_t)s0 * 256 + 128 + lane * 4));
        float t0 = (q4.x * k0.x + q4.y * k0.y + q4.z * k0.z + q4.w * k0.w) * 0.25f;
        t0 += __shfl_xor_sync(0xffffffffu, t0, 1);
        t0 += __shfl_xor_sync(0xffffffffu, t0, 2);
        const float e0 = __expf(t0 + b0);
        den += e0;
        acc.x = fmaf(e0, v0.x, acc.x);
        acc.y = fmaf(e0, v0.y, acc.y);
        acc.z = fmaf(e0, v0.z, acc.z);
        acc.w = fmaf(e0, v0.w, acc.w);
    }

    const float inv = (den > 0.f) ? (1.f / den) : 0.f;
    float* o = out + (size_t)d * 128 + lane * 4;
    *(float4*)o = make_float4(acc.x * inv, acc.y * inv, acc.z * inv, acc.w * inv);
}

// ---------------------------------------------------------------------------
extern "C" void kernel_launch(void* const* d_in, const int* in_sizes, int n_in,
                              void* d_out, int out_size) {
    const float* x     = (const float*)d_in[0];
    const int*   ei    = (const int*)  d_in[1];
    const float* eattr = (const float*)d_in[2];
    const float* Wq    = (const float*)d_in[3];
    const float* Wk    = (const float*)d_in[4];
    const float* Wv    = (const float*)d_in[5];
    const float* We    = (const float*)d_in[6];
    float* out = (float*)d_out;

    cudaFuncSetAttribute(k_projMMA, cudaFuncAttributeMaxDynamicSharedMemorySize,
                         SM_FLOATS * (int)sizeof(float));

    // fork: projection on side stream
    cudaEventRecord(g_hx.fork, 0);
    cudaStreamWaitEvent(g_hx.s2, g_hx.fork, 0);
    dim3 pg((Nn + 127) / 128, 3);
    k_projMMA<<<pg, 256, SM_FLOATS * sizeof(float), g_hx.s2>>>(x, Wq, Wk, Wv);
    cudaEventRecord(g_hx.join, g_hx.s2);

    // edge-sort chain on main stream
    k_zero   <<<NB, 256>>>();
    k_hist   <<<(Ee + 255) / 256, 256>>>(ei);
    k_scan1  <<<NB, 256>>>();
    k_scan2  <<<1, 512>>>();
    k_scan3  <<<NB, 256>>>();
    k_scatter<<<(Ee + 255) / 256, 256>>>(ei, eattr, We);

    // join: fused pass needs both
    cudaStreamWaitEvent(0, g_hx.join, 0);
    k_fused  <<<(Nn + 7) / 8, 256>>>(out);
}

// round 9
// speedup vs baseline: 1.0212x; 1.0212x over previous
#include <cuda_runtime.h>
#include <cstdint>

#define Nn 100000
#define Ee 1600000
#define Hh 8
#define HC 128   // H*C == DIM
#define NB 391   // ceil(Nn/256)

// ---- scratch (device globals; no allocation allowed) ----
__device__ float g_q[(size_t)Nn * HC];
__device__ float g_k[(size_t)Nn * HC];
__device__ float g_v[(size_t)Nn * HC];
__device__ float g_biasS[(size_t)Ee * Hh];   // bias (sorted) -> overwritten with ex in pass 1
__device__ float g_den[(size_t)Nn * Hh];
__device__ int   g_cnt[Nn];
__device__ int   g_off[Nn + 1];
__device__ int   g_pos[Nn];
__device__ int   g_bsum[512];
__device__ int   g_src[Ee];                  // src node, sorted by dst

// ---- host-side fork/join resources (created once; NOT device memory) ----
struct HxStreams {
    cudaStream_t s2;
    cudaEvent_t  fork, join;
    HxStreams() {
        cudaStreamCreateWithFlags(&s2, cudaStreamNonBlocking);
        cudaEventCreateWithFlags(&fork, cudaEventDisableTiming);
        cudaEventCreateWithFlags(&join, cudaEventDisableTiming);
    }
};
static HxStreams g_hx;

// ===========================================================================
// tf32 helpers (base PTX, works on compute_103)
// ===========================================================================
__device__ __forceinline__ float tf32_rna(float f) {
    uint32_t u;
    asm("cvt.rna.tf32.f32 %0, %1;" : "=r"(u) : "f"(f));
    return __uint_as_float(u);
}

__device__ __forceinline__ void mma8(float* d, const uint32_t* a,
                                     uint32_t b0, uint32_t b1) {
    asm volatile(
        "mma.sync.aligned.m16n8k8.row.col.f32.tf32.tf32.f32 "
        "{%0,%1,%2,%3}, {%4,%5,%6,%7}, {%8,%9}, {%0,%1,%2,%3};"
        : "+f"(d[0]), "+f"(d[1]), "+f"(d[2]), "+f"(d[3])
        : "r"(a[0]), "r"(a[1]), "r"(a[2]), "r"(a[3]), "r"(b0), "r"(b1));
}

// ===========================================================================
// projections via tensor cores (3xTF32): q/k/v = x @ W.T
// ===========================================================================
#define KC   32
#define PAD  36
#define SM_FLOATS (4 * 128 * PAD)

__global__ __launch_bounds__(256, 2) void k_projMMA(
    const float* __restrict__ x,
    const float* __restrict__ Wq,
    const float* __restrict__ Wk,
    const float* __restrict__ Wv)
{
    extern __shared__ float sm[];
    float* AsH = sm;
    float* AsL = AsH + 128 * PAD;
    float* BsH = AsL + 128 * PAD;
    float* BsL = BsH + 128 * PAD;

    const int tid   = threadIdx.x;
    const int wid   = tid >> 5;
    const int lane  = tid & 31;
    const int warpM = wid & 3;
    const int warpN = wid >> 2;
    const int gr    = lane >> 2;
    const int qt    = lane & 3;
    const int row0  = blockIdx.x * 128;

    const float* W  = (blockIdx.y == 0) ? Wq : (blockIdx.y == 1) ? Wk : Wv;
    float*  outp    = (blockIdx.y == 0) ? g_q : (blockIdx.y == 1) ? g_k : g_v;

    float d[2][8][4];
#pragma unroll
    for (int mf = 0; mf < 2; mf++)
#pragma unroll
        for (int nf = 0; nf < 8; nf++)
#pragma unroll
            for (int i = 0; i < 4; i++) d[mf][nf][i] = 0.f;

#pragma unroll 1
    for (int kc = 0; kc < 128; kc += KC) {
#pragma unroll
        for (int it = 0; it < 4; it++) {
            int lin = tid + it * 256;
            int r   = lin >> 3;
            int c4  = (lin & 7) << 2;
            float4 v = make_float4(0.f, 0.f, 0.f, 0.f);
            if (row0 + r < Nn)
                v = *(const float4*)(x + (size_t)(row0 + r) * 128 + kc + c4);
            float4 hi = make_float4(tf32_rna(v.x), tf32_rna(v.y), tf32_rna(v.z), tf32_rna(v.w));
            float4 lo = make_float4(tf32_rna(v.x - hi.x), tf32_rna(v.y - hi.y),
                                    tf32_rna(v.z - hi.z), tf32_rna(v.w - hi.w));
            *(float4*)(AsH + r * PAD + c4) = hi;
            *(float4*)(AsL + r * PAD + c4) = lo;

            float4 w = *(const float4*)(W + (size_t)r * 128 + kc + c4);
            float4 wh = make_float4(tf32_rna(w.x), tf32_rna(w.y), tf32_rna(w.z), tf32_rna(w.w));
            float4 wl = make_float4(tf32_rna(w.x - wh.x), tf32_rna(w.y - wh.y),
                                    tf32_rna(w.z - wh.z), tf32_rna(w.w - wh.w));
            *(float4*)(BsH + r * PAD + c4) = wh;
            *(float4*)(BsL + r * PAD + c4) = wl;
        }
        __syncthreads();

#pragma unroll
        for (int k0 = 0; k0 < KC; k0 += 8) {
            uint32_t aH[2][4], aL[2][4];
#pragma unroll
            for (int mf = 0; mf < 2; mf++) {
                const float* pH = AsH + (warpM * 32 + mf * 16 + gr) * PAD + k0 + qt;
                const float* pL = AsL + (warpM * 32 + mf * 16 + gr) * PAD + k0 + qt;
                aH[mf][0] = __float_as_uint(pH[0]);
                aH[mf][1] = __float_as_uint(pH[8 * PAD]);
                aH[mf][2] = __float_as_uint(pH[4]);
                aH[mf][3] = __float_as_uint(pH[8 * PAD + 4]);
                aL[mf][0] = __float_as_uint(pL[0]);
                aL[mf][1] = __float_as_uint(pL[8 * PAD]);
                aL[mf][2] = __float_as_uint(pL[4]);
                aL[mf][3] = __float_as_uint(pL[8 * PAD + 4]);
            }
#pragma unroll
            for (int nf = 0; nf < 8; nf++) {
                const float* pBH = BsH + (warpN * 64 + nf * 8 + gr) * PAD + k0 + qt;
                const float* pBL = BsL + (warpN * 64 + nf * 8 + gr) * PAD + k0 + qt;
                uint32_t bh0 = __float_as_uint(pBH[0]);
                uint32_t bh1 = __float_as_uint(pBH[4]);
                uint32_t bl0 = __float_as_uint(pBL[0]);
                uint32_t bl1 = __float_as_uint(pBL[4]);
                mma8(d[0][nf], aH[0], bh0, bh1);
                mma8(d[1][nf], aH[1], bh0, bh1);
                mma8(d[0][nf], aH[0], bl0, bl1);
                mma8(d[1][nf], aH[1], bl0, bl1);
                mma8(d[0][nf], aL[0], bh0, bh1);
                mma8(d[1][nf], aL[1], bh0, bh1);
            }
        }
        __syncthreads();
    }

#pragma unroll
    for (int mf = 0; mf < 2; mf++) {
        int r = row0 + warpM * 32 + mf * 16 + gr;
#pragma unroll
        for (int nf = 0; nf < 8; nf++) {
            int c = warpN * 64 + nf * 8 + qt * 2;
            if (r < Nn)
                *(float2*)(outp + (size_t)r * 128 + c) = make_float2(d[mf][nf][0], d[mf][nf][1]);
            if (r + 8 < Nn)
                *(float2*)(outp + (size_t)(r + 8) * 128 + c) = make_float2(d[mf][nf][2], d[mf][nf][3]);
        }
    }
}

// ---------------------------------------------------------------------------
__global__ void k_zero() {
    int i = blockIdx.x * 256 + threadIdx.x;
    if (i < Nn) g_cnt[i] = 0;
}

// ---------------------------------------------------------------------------
// counting sort by dst: histogram -> scan -> scatter(+bias)
// ---------------------------------------------------------------------------
__global__ void k_hist(const int* __restrict__ ei) {
    int e = blockIdx.x * 256 + threadIdx.x;
    if (e < Ee) atomicAdd(&g_cnt[ei[Ee + e]], 1);
}

__global__ void k_scan1() {
    __shared__ int sh[256];
    int i = blockIdx.x * 256 + threadIdx.x;
    int v = (i < Nn) ? g_cnt[i] : 0;
    sh[threadIdx.x] = v;
    __syncthreads();
#pragma unroll
    for (int s = 128; s > 0; s >>= 1) {
        if (threadIdx.x < s) sh[threadIdx.x] += sh[threadIdx.x + s];
        __syncthreads();
    }
    if (threadIdx.x == 0) g_bsum[blockIdx.x] = sh[0];
}

__global__ void k_scan2() {
    __shared__ int sh[512];
    int t = threadIdx.x;
    sh[t] = (t < NB) ? g_bsum[t] : 0;
    __syncthreads();
#pragma unroll
    for (int s = 1; s < 512; s <<= 1) {
        int add = (t >= s) ? sh[t - s] : 0;
        __syncthreads();
        sh[t] += add;
        __syncthreads();
    }
    if (t < NB) g_bsum[t] = (t == 0) ? 0 : sh[t - 1];
    if (t == 0) g_off[Nn] = Ee;
}

__global__ void k_scan3() {
    __shared__ int sh[256];
    int i = blockIdx.x * 256 + threadIdx.x;
    int t = threadIdx.x;
    int v = (i < Nn) ? g_cnt[i] : 0;
    sh[t] = v;
    __syncthreads();
#pragma unroll
    for (int s = 1; s < 256; s <<= 1) {
        int add = (t >= s) ? sh[t - s] : 0;
        __syncthreads();
        sh[t] += add;
        __syncthreads();
    }
    if (i < Nn) {
        int off = g_bsum[blockIdx.x] + sh[t] - v;
        g_off[i] = off;
        g_pos[i] = off;
    }
}

// scatter + edge-bias precompute into sorted order
__global__ __launch_bounds__(256) void k_scatter(
    const int* __restrict__ ei,
    const float* __restrict__ eattr,
    const float* __restrict__ We)
{
    __shared__ float We_s[256];
    We_s[threadIdx.x] = We[threadIdx.x];
    __syncthreads();

    int e = blockIdx.x * 256 + threadIdx.x;
    if (e >= Ee) return;
    int src = ei[e];
    int dst = ei[Ee + e];
    int p = atomicAdd(&g_pos[dst], 1);
    g_src[p] = src;

    float4 a[8];
    const float4* ap = (const float4*)(eattr + (size_t)e * 32);
#pragma unroll
    for (int i = 0; i < 8; i++) a[i] = __ldg(ap + i);

    float b[8];
#pragma unroll
    for (int h = 0; h < 8; h++) {
        const float* w = We_s + h * 32;
        float s = 0.f;
#pragma unroll
        for (int i = 0; i < 8; i++) {
            s = fmaf(a[i].x, w[i * 4 + 0], s);
            s = fmaf(a[i].y, w[i * 4 + 1], s);
            s = fmaf(a[i].z, w[i * 4 + 2], s);
            s = fmaf(a[i].w, w[i * 4 + 3], s);
        }
        b[h] = s;
    }
    float* bp = g_biasS + (size_t)p * 8;
    *(float4*)(bp)     = make_float4(b[0], b[1], b[2], b[3]);
    *(float4*)(bp + 4) = make_float4(b[4], b[5], b[6], b[7]);
}

// ---------------------------------------------------------------------------
// pass 1: scores. one warp per dst. gathers ONLY k (51MB table, L2-resident).
// ex = exp(q.k + bias) overwrites the bias slot in place; den -> g_den.
// ---------------------------------------------------------------------------
__global__ __launch_bounds__(256) void k_pass1()
{
    const int warp = threadIdx.x >> 5;
    const int lane = threadIdx.x & 31;
    const int d = blockIdx.x * 8 + warp;
    if (d >= Nn) return;

    const int beg = g_off[d];
    const int end = g_off[d + 1];
    const int g = lane >> 2, r = lane & 3;

    const float4 q4 = __ldg((const float4*)(g_q + (size_t)d * 128 + lane * 4));

    float den = 0.f;
    int p = beg;
    const int n2 = beg + ((end - beg) & ~1);
#pragma unroll 1
    for (; p < n2; p += 2) {
        const int s0 = __ldg(g_src + p);
        const int s1 = __ldg(g_src + p + 1);
        const float b0 = __ldg(g_biasS + (size_t)p * 8 + g);
        const float b1 = __ldg(g_biasS + (size_t)(p + 1) * 8 + g);
        const float4 k0 = __ldg((const float4*)(g_k + (size_t)s0 * 128 + lane * 4));
        const float4 k1 = __ldg((const float4*)(g_k + (size_t)s1 * 128 + lane * 4));

        float t0 = (q4.x * k0.x + q4.y * k0.y + q4.z * k0.z + q4.w * k0.w) * 0.25f;
        float t1 = (q4.x * k1.x + q4.y * k1.y + q4.z * k1.z + q4.w * k1.w) * 0.25f;
        t0 += __shfl_xor_sync(0xffffffffu, t0, 1);
        t0 += __shfl_xor_sync(0xffffffffu, t0, 2);
        t1 += __shfl_xor_sync(0xffffffffu, t1, 1);
        t1 += __shfl_xor_sync(0xffffffffu, t1, 2);

        const float e0 = __expf(t0 + b0);
        const float e1 = __expf(t1 + b1);
        den += e0 + e1;
        if (r == 0) {
            g_biasS[(size_t)p * 8 + g]       = e0;
            g_biasS[(size_t)(p + 1) * 8 + g] = e1;
        }
    }
    if (p < end) {
        const int s0 = __ldg(g_src + p);
        const float b0 = __ldg(g_biasS + (size_t)p * 8 + g);
        const float4 k0 = __ldg((const float4*)(g_k + (size_t)s0 * 128 + lane * 4));
        float t0 = (q4.x * k0.x + q4.y * k0.y + q4.z * k0.z + q4.w * k0.w) * 0.25f;
        t0 += __shfl_xor_sync(0xffffffffu, t0, 1);
        t0 += __shfl_xor_sync(0xffffffffu, t0, 2);
        const float e0 = __expf(t0 + b0);
        den += e0;
        if (r == 0) g_biasS[(size_t)p * 8 + g] = e0;
    }

    if (r == 0) g_den[(size_t)d * 8 + g] = den;
}

// ---------------------------------------------------------------------------
// pass 2: aggregate. one warp per dst. gathers ONLY v (51MB table, L2-resident).
// ---------------------------------------------------------------------------
__global__ __launch_bounds__(256) void k_pass2(float* __restrict__ out)
{
    const int warp = threadIdx.x >> 5;
    const int lane = threadIdx.x & 31;
    const int d = blockIdx.x * 8 + warp;
    if (d >= Nn) return;

    const int beg = g_off[d];
    const int end = g_off[d + 1];
    const int g = lane >> 2;

    float4 acc = make_float4(0.f, 0.f, 0.f, 0.f);

    int p = beg;
    const int n2 = beg + ((end - beg) & ~1);
#pragma unroll 1
    for (; p < n2; p += 2) {
        const int s0 = __ldg(g_src + p);
        const int s1 = __ldg(g_src + p + 1);
        const float e0 = __ldg(g_biasS + (size_t)p * 8 + g);
        const float e1 = __ldg(g_biasS + (size_t)(p + 1) * 8 + g);
        const float4 v0 = __ldg((const float4*)(g_v + (size_t)s0 * 128 + lane * 4));
        const float4 v1 = __ldg((const float4*)(g_v + (size_t)s1 * 128 + lane * 4));
        acc.x = fmaf(e0, v0.x, fmaf(e1, v1.x, acc.x));
        acc.y = fmaf(e0, v0.y, fmaf(e1, v1.y, acc.y));
        acc.z = fmaf(e0, v0.z, fmaf(e1, v1.z, acc.z));
        acc.w = fmaf(e0, v0.w, fmaf(e1, v1.w, acc.w));
    }
    if (p < end) {
        const int s0 = __ldg(g_src + p);
        const float e0 = __ldg(g_biasS + (size_t)p * 8 + g);
        const float4 v0 = __ldg((const float4*)(g_v + (size_t)s0 * 128 + lane * 4));
        acc.x = fmaf(e0, v0.x, acc.x);
        acc.y = fmaf(e0, v0.y, acc.y);
        acc.z = fmaf(e0, v0.z, acc.z);
        acc.w = fmaf(e0, v0.w, acc.w);
    }

    const float den = __ldg(g_den + (size_t)d * 8 + g);
    const float inv = (den > 0.f) ? (1.f / den) : 0.f;
    float* o = out + (size_t)d * 128 + lane * 4;
    *(float4*)o = make_float4(acc.x * inv, acc.y * inv, acc.z * inv, acc.w * inv);
}

// ---------------------------------------------------------------------------
extern "C" void kernel_launch(void* const* d_in, const int* in_sizes, int n_in,
                              void* d_out, int out_size) {
    const float* x     = (const float*)d_in[0];
    const int*   ei    = (const int*)  d_in[1];
    const float* eattr = (const float*)d_in[2];
    const float* Wq    = (const float*)d_in[3];
    const float* Wk    = (const float*)d_in[4];
    const float* Wv    = (const float*)d_in[5];
    const float* We    = (const float*)d_in[6];
    float* out = (float*)d_out;

    cudaFuncSetAttribute(k_projMMA, cudaFuncAttributeMaxDynamicSharedMemorySize,
                         SM_FLOATS * (int)sizeof(float));

    // fork: projection on side stream
    cudaEventRecord(g_hx.fork, 0);
    cudaStreamWaitEvent(g_hx.s2, g_hx.fork, 0);
    dim3 pg((Nn + 127) / 128, 3);
    k_projMMA<<<pg, 256, SM_FLOATS * sizeof(float), g_hx.s2>>>(x, Wq, Wk, Wv);
    cudaEventRecord(g_hx.join, g_hx.s2);

    // edge-sort chain on main stream
    k_zero   <<<NB, 256>>>();
    k_hist   <<<(Ee + 255) / 256, 256>>>(ei);
    k_scan1  <<<NB, 256>>>();
    k_scan2  <<<1, 512>>>();
    k_scan3  <<<NB, 256>>>();
    k_scatter<<<(Ee + 255) / 256, 256>>>(ei, eattr, We);

    // join: edge passes need projections too
    cudaStreamWaitEvent(0, g_hx.join, 0);
    k_pass1  <<<(Nn + 7) / 8, 256>>>();
    k_pass2  <<<(Nn + 7) / 8, 256>>>(out);
}

// round 10
// speedup vs baseline: 1.0991x; 1.0763x over previous
#include <cuda_runtime.h>
#include <cstdint>

#define Nn 100000
#define Ee 1600000
#define Hh 8
#define HC 128   // H*C == DIM
#define NB 391   // ceil(Nn/256)

// ---- scratch (device globals; no allocation allowed) ----
__device__ float g_q[(size_t)Nn * HC];
__device__ float g_k[(size_t)Nn * HC];
__device__ float g_v[(size_t)Nn * HC];
__device__ float g_biasS[(size_t)Ee * Hh];   // bias (sorted) -> overwritten with ex in pass 1
__device__ float g_den[(size_t)Nn * Hh];
__device__ int   g_cnt[Nn];
__device__ int   g_off[Nn + 1];
__device__ int   g_pos[Nn];
__device__ int   g_bsum[512];
__device__ int   g_src[Ee];                  // src node, sorted by dst

// ---- host-side fork/join resources (created once; NOT device memory) ----
struct HxStreams {
    cudaStream_t s2;
    cudaEvent_t  fork, join;
    HxStreams() {
        cudaStreamCreateWithFlags(&s2, cudaStreamNonBlocking);
        cudaEventCreateWithFlags(&fork, cudaEventDisableTiming);
        cudaEventCreateWithFlags(&join, cudaEventDisableTiming);
    }
};
static HxStreams g_hx;

// ===========================================================================
// tf32 helpers (base PTX, works on compute_103)
// ===========================================================================
__device__ __forceinline__ float tf32_rna(float f) {
    uint32_t u;
    asm("cvt.rna.tf32.f32 %0, %1;" : "=r"(u) : "f"(f));
    return __uint_as_float(u);
}

__device__ __forceinline__ void mma8(float* d, const uint32_t* a,
                                     uint32_t b0, uint32_t b1) {
    asm volatile(
        "mma.sync.aligned.m16n8k8.row.col.f32.tf32.tf32.f32 "
        "{%0,%1,%2,%3}, {%4,%5,%6,%7}, {%8,%9}, {%0,%1,%2,%3};"
        : "+f"(d[0]), "+f"(d[1]), "+f"(d[2]), "+f"(d[3])
        : "r"(a[0]), "r"(a[1]), "r"(a[2]), "r"(a[3]), "r"(b0), "r"(b1));
}

// ===========================================================================
// projections via tensor cores (3xTF32): q/k/v = x @ W.T
// ===========================================================================
#define KC   32
#define PAD  36
#define SM_FLOATS (4 * 128 * PAD)

__global__ __launch_bounds__(256, 2) void k_projMMA(
    const float* __restrict__ x,
    const float* __restrict__ Wq,
    const float* __restrict__ Wk,
    const float* __restrict__ Wv)
{
    extern __shared__ float sm[];
    float* AsH = sm;
    float* AsL = AsH + 128 * PAD;
    float* BsH = AsL + 128 * PAD;
    float* BsL = BsH + 128 * PAD;

    const int tid   = threadIdx.x;
    const int wid   = tid >> 5;
    const int lane  = tid & 31;
    const int warpM = wid & 3;
    const int warpN = wid >> 2;
    const int gr    = lane >> 2;
    const int qt    = lane & 3;
    const int row0  = blockIdx.x * 128;

    const float* W  = (blockIdx.y == 0) ? Wq : (blockIdx.y == 1) ? Wk : Wv;
    float*  outp    = (blockIdx.y == 0) ? g_q : (blockIdx.y == 1) ? g_k : g_v;

    float d[2][8][4];
#pragma unroll
    for (int mf = 0; mf < 2; mf++)
#pragma unroll
        for (int nf = 0; nf < 8; nf++)
#pragma unroll
            for (int i = 0; i < 4; i++) d[mf][nf][i] = 0.f;

#pragma unroll 1
    for (int kc = 0; kc < 128; kc += KC) {
#pragma unroll
        for (int it = 0; it < 4; it++) {
            int lin = tid + it * 256;
            int r   = lin >> 3;
            int c4  = (lin & 7) << 2;
            float4 v = make_float4(0.f, 0.f, 0.f, 0.f);
            if (row0 + r < Nn)
                v = *(const float4*)(x + (size_t)(row0 + r) * 128 + kc + c4);
            float4 hi = make_float4(tf32_rna(v.x), tf32_rna(v.y), tf32_rna(v.z), tf32_rna(v.w));
            float4 lo = make_float4(tf32_rna(v.x - hi.x), tf32_rna(v.y - hi.y),
                                    tf32_rna(v.z - hi.z), tf32_rna(v.w - hi.w));
            *(float4*)(AsH + r * PAD + c4) = hi;
            *(float4*)(AsL + r * PAD + c4) = lo;

            float4 w = *(const float4*)(W + (size_t)r * 128 + kc + c4);
            float4 wh = make_float4(tf32_rna(w.x), tf32_rna(w.y), tf32_rna(w.z), tf32_rna(w.w));
            float4 wl = make_float4(tf32_rna(w.x - wh.x), tf32_rna(w.y - wh.y),
                                    tf32_rna(w.z - wh.z), tf32_rna(w.w - wh.w));
            *(float4*)(BsH + r * PAD + c4) = wh;
            *(float4*)(BsL + r * PAD + c4) = wl;
        }
        __syncthreads();

#pragma unroll
        for (int k0 = 0; k0 < KC; k0 += 8) {
            uint32_t aH[2][4], aL[2][4];
#pragma unroll
            for (int mf = 0; mf < 2; mf++) {
                const float* pH = AsH + (warpM * 32 + mf * 16 + gr) * PAD + k0 + qt;
                const float* pL = AsL + (warpM * 32 + mf * 16 + gr) * PAD + k0 + qt;
                aH[mf][0] = __float_as_uint(pH[0]);
                aH[mf][1] = __float_as_uint(pH[8 * PAD]);
                aH[mf][2] = __float_as_uint(pH[4]);
                aH[mf][3] = __float_as_uint(pH[8 * PAD + 4]);
                aL[mf][0] = __float_as_uint(pL[0]);
                aL[mf][1] = __float_as_uint(pL[8 * PAD]);
                aL[mf][2] = __float_as_uint(pL[4]);
                aL[mf][3] = __float_as_uint(pL[8 * PAD + 4]);
            }
#pragma unroll
            for (int nf = 0; nf < 8; nf++) {
                const float* pBH = BsH + (warpN * 64 + nf * 8 + gr) * PAD + k0 + qt;
                const float* pBL = BsL + (warpN * 64 + nf * 8 + gr) * PAD + k0 + qt;
                uint32_t bh0 = __float_as_uint(pBH[0]);
                uint32_t bh1 = __float_as_uint(pBH[4]);
                uint32_t bl0 = __float_as_uint(pBL[0]);
                uint32_t bl1 = __float_as_uint(pBL[4]);
                mma8(d[0][nf], aH[0], bh0, bh1);
                mma8(d[1][nf], aH[1], bh0, bh1);
                mma8(d[0][nf], aH[0], bl0, bl1);
                mma8(d[1][nf], aH[1], bl0, bl1);
                mma8(d[0][nf], aL[0], bh0, bh1);
                mma8(d[1][nf], aL[1], bh0, bh1);
            }
        }
        __syncthreads();
    }

#pragma unroll
    for (int mf = 0; mf < 2; mf++) {
        int r = row0 + warpM * 32 + mf * 16 + gr;
#pragma unroll
        for (int nf = 0; nf < 8; nf++) {
            int c = warpN * 64 + nf * 8 + qt * 2;
            if (r < Nn)
                *(float2*)(outp + (size_t)r * 128 + c) = make_float2(d[mf][nf][0], d[mf][nf][1]);
            if (r + 8 < Nn)
                *(float2*)(outp + (size_t)(r + 8) * 128 + c) = make_float2(d[mf][nf][2], d[mf][nf][3]);
        }
    }
}

// ---------------------------------------------------------------------------
__global__ void k_zero() {
    int i = blockIdx.x * 256 + threadIdx.x;
    if (i < Nn) g_cnt[i] = 0;
}

// ---------------------------------------------------------------------------
// counting sort by dst: histogram -> scan -> scatter(+bias)
// ---------------------------------------------------------------------------
__global__ void k_hist(const int* __restrict__ ei) {
    int e = blockIdx.x * 256 + threadIdx.x;
    if (e < Ee) atomicAdd(&g_cnt[ei[Ee + e]], 1);
}

__global__ void k_scan1() {
    __shared__ int sh[256];
    int i = blockIdx.x * 256 + threadIdx.x;
    int v = (i < Nn) ? g_cnt[i] : 0;
    sh[threadIdx.x] = v;
    __syncthreads();
#pragma unroll
    for (int s = 128; s > 0; s >>= 1) {
        if (threadIdx.x < s) sh[threadIdx.x] += sh[threadIdx.x + s];
        __syncthreads();
    }
    if (threadIdx.x == 0) g_bsum[blockIdx.x] = sh[0];
}

__global__ void k_scan2() {
    __shared__ int sh[512];
    int t = threadIdx.x;
    sh[t] = (t < NB) ? g_bsum[t] : 0;
    __syncthreads();
#pragma unroll
    for (int s = 1; s < 512; s <<= 1) {
        int add = (t >= s) ? sh[t - s] : 0;
        __syncthreads();
        sh[t] += add;
        __syncthreads();
    }
    if (t < NB) g_bsum[t] = (t == 0) ? 0 : sh[t - 1];
    if (t == 0) g_off[Nn] = Ee;
}

__global__ void k_scan3() {
    __shared__ int sh[256];
    int i = blockIdx.x * 256 + threadIdx.x;
    int t = threadIdx.x;
    int v = (i < Nn) ? g_cnt[i] : 0;
    sh[t] = v;
    __syncthreads();
#pragma unroll
    for (int s = 1; s < 256; s <<= 1) {
        int add = (t >= s) ? sh[t - s] : 0;
        __syncthreads();
        sh[t] += add;
        __syncthreads();
    }
    if (i < Nn) {
        int off = g_bsum[blockIdx.x] + sh[t] - v;
        g_off[i] = off;
        g_pos[i] = off;
    }
}

// ---------------------------------------------------------------------------
// scatter + edge-bias precompute. eattr staged through smem so global loads
// are fully coalesced (nL=4/LDG instead of 32).
// ---------------------------------------------------------------------------
__global__ __launch_bounds__(256) void k_scatter(
    const int* __restrict__ ei,
    const float* __restrict__ eattr,
    const float* __restrict__ We)
{
    __shared__ float We_s[256];
    __shared__ float at[256 * 33];     // 256 edges x 32 attrs, stride 33
    We_s[threadIdx.x] = We[threadIdx.x];

    const int tid = threadIdx.x;
    const int e0  = blockIdx.x * 256;

    // coalesced load of this block's 256x32 attr slab
    const float4* src4 = (const float4*)(eattr + (size_t)e0 * 32);
#pragma unroll
    for (int i = 0; i < 8; i++) {
        int f = i * 256 + tid;          // float4 index within slab (0..2047)
        int row = f >> 3;
        int col = (f & 7) << 2;
        if (e0 + row < Ee) {
            float4 v = __ldg(src4 + f);
            float* dst = at + row * 33 + col;
            dst[0] = v.x; dst[1] = v.y; dst[2] = v.z; dst[3] = v.w;
        }
    }
    __syncthreads();

    int e = e0 + tid;
    if (e >= Ee) return;
    int src = ei[e];
    int dst = ei[Ee + e];
    int p = atomicAdd(&g_pos[dst], 1);
    g_src[p] = src;

    float a[32];
    const float* ar = at + tid * 33;
#pragma unroll
    for (int i = 0; i < 32; i++) a[i] = ar[i];

    float b[8];
#pragma unroll
    for (int h = 0; h < 8; h++) {
        const float* w = We_s + h * 32;
        float s = 0.f;
#pragma unroll
        for (int i = 0; i < 32; i++) s = fmaf(a[i], w[i], s);
        b[h] = s;
    }
    float* bp = g_biasS + (size_t)p * 8;
    *(float4*)(bp)     = make_float4(b[0], b[1], b[2], b[3]);
    *(float4*)(bp + 4) = make_float4(b[4], b[5], b[6], b[7]);
}

// ---------------------------------------------------------------------------
// pass 1: scores. one warp per dst, unroll x4. gathers ONLY k.
// ---------------------------------------------------------------------------
__global__ __launch_bounds__(256) void k_pass1()
{
    const int warp = threadIdx.x >> 5;
    const int lane = threadIdx.x & 31;
    const int d = blockIdx.x * 8 + warp;
    if (d >= Nn) return;

    const int beg = g_off[d];
    const int end = g_off[d + 1];
    const int g = lane >> 2, r = lane & 3;

    const float4 q4 = __ldg((const float4*)(g_q + (size_t)d * 128 + lane * 4));

    float den = 0.f;
    int p = beg;
    const int n4 = beg + ((end - beg) & ~3);
#pragma unroll 1
    for (; p < n4; p += 4) {
        int   s[4]; float b[4]; float4 kk[4];
#pragma unroll
        for (int j = 0; j < 4; j++) s[j] = __ldg(g_src + p + j);
#pragma unroll
        for (int j = 0; j < 4; j++) b[j] = __ldg(g_biasS + (size_t)(p + j) * 8 + g);
#pragma unroll
        for (int j = 0; j < 4; j++)
            kk[j] = __ldg((const float4*)(g_k + (size_t)s[j] * 128 + lane * 4));

        float t[4];
#pragma unroll
        for (int j = 0; j < 4; j++)
            t[j] = (q4.x * kk[j].x + q4.y * kk[j].y + q4.z * kk[j].z + q4.w * kk[j].w) * 0.25f;
#pragma unroll
        for (int j = 0; j < 4; j++) {
            t[j] += __shfl_xor_sync(0xffffffffu, t[j], 1);
            t[j] += __shfl_xor_sync(0xffffffffu, t[j], 2);
        }
#pragma unroll
        for (int j = 0; j < 4; j++) {
            float e = __expf(t[j] + b[j]);
            den += e;
            if (r == 0) g_biasS[(size_t)(p + j) * 8 + g] = e;
        }
    }
#pragma unroll 1
    for (; p < end; p++) {
        const int s0 = __ldg(g_src + p);
        const float b0 = __ldg(g_biasS + (size_t)p * 8 + g);
        const float4 k0 = __ldg((const float4*)(g_k + (size_t)s0 * 128 + lane * 4));
        float t0 = (q4.x * k0.x + q4.y * k0.y + q4.z * k0.z + q4.w * k0.w) * 0.25f;
        t0 += __shfl_xor_sync(0xffffffffu, t0, 1);
        t0 += __shfl_xor_sync(0xffffffffu, t0, 2);
        const float e0 = __expf(t0 + b0);
        den += e0;
        if (r == 0) g_biasS[(size_t)p * 8 + g] = e0;
    }

    if (r == 0) g_den[(size_t)d * 8 + g] = den;
}

// ---------------------------------------------------------------------------
// pass 2: aggregate. one warp per dst, unroll x4. gathers ONLY v.
// ---------------------------------------------------------------------------
__global__ __launch_bounds__(256) void k_pass2(float* __restrict__ out)
{
    const int warp = threadIdx.x >> 5;
    const int lane = threadIdx.x & 31;
    const int d = blockIdx.x * 8 + warp;
    if (d >= Nn) return;

    const int beg = g_off[d];
    const int end = g_off[d + 1];
    const int g = lane >> 2;

    float4 acc = make_float4(0.f, 0.f, 0.f, 0.f);

    int p = beg;
    const int n4 = beg + ((end - beg) & ~3);
#pragma unroll 1
    for (; p < n4; p += 4) {
        int s[4]; float e[4]; float4 vv[4];
#pragma unroll
        for (int j = 0; j < 4; j++) s[j] = __ldg(g_src + p + j);
#pragma unroll
        for (int j = 0; j < 4; j++) e[j] = __ldg(g_biasS + (size_t)(p + j) * 8 + g);
#pragma unroll
        for (int j = 0; j < 4; j++)
            vv[j] = __ldg((const float4*)(g_v + (size_t)s[j] * 128 + lane * 4));
#pragma unroll
        for (int j = 0; j < 4; j++) {
            acc.x = fmaf(e[j], vv[j].x, acc.x);
            acc.y = fmaf(e[j], vv[j].y, acc.y);
            acc.z = fmaf(e[j], vv[j].z, acc.z);
            acc.w = fmaf(e[j], vv[j].w, acc.w);
        }
    }
#pragma unroll 1
    for (; p < end; p++) {
        const int s0 = __ldg(g_src + p);
        const float e0 = __ldg(g_biasS + (size_t)p * 8 + g);
        const float4 v0 = __ldg((const float4*)(g_v + (size_t)s0 * 128 + lane * 4));
        acc.x = fmaf(e0, v0.x, acc.x);
        acc.y = fmaf(e0, v0.y, acc.y);
        acc.z = fmaf(e0, v0.z, acc.z);
        acc.w = fmaf(e0, v0.w, acc.w);
    }

    const float den = __ldg(g_den + (size_t)d * 8 + g);
    const float inv = (den > 0.f) ? (1.f / den) : 0.f;
    float* o = out + (size_t)d * 128 + lane * 4;
    *(float4*)o = make_float4(acc.x * inv, acc.y * inv, acc.z * inv, acc.w * inv);
}

// ---------------------------------------------------------------------------
extern "C" void kernel_launch(void* const* d_in, const int* in_sizes, int n_in,
                              void* d_out, int out_size) {
    const float* x     = (const float*)d_in[0];
    const int*   ei    = (const int*)  d_in[1];
    const float* eattr = (const float*)d_in[2];
    const float* Wq    = (const float*)d_in[3];
    const float* Wk    = (const float*)d_in[4];
    const float* Wv    = (const float*)d_in[5];
    const float* We    = (const float*)d_in[6];
    float* out = (float*)d_out;

    cudaFuncSetAttribute(k_projMMA, cudaFuncAttributeMaxDynamicSharedMemorySize,
                         SM_FLOATS * (int)sizeof(float));

    // fork: projection on side stream
    cudaEventRecord(g_hx.fork, 0);
    cudaStreamWaitEvent(g_hx.s2, g_hx.fork, 0);
    dim3 pg((Nn + 127) / 128, 3);
    k_projMMA<<<pg, 256, SM_FLOATS * sizeof(float), g_hx.s2>>>(x, Wq, Wk, Wv);
    cudaEventRecord(g_hx.join, g_hx.s2);

    // edge-sort chain on main stream
    k_zero   <<<NB, 256>>>();
    k_hist   <<<(Ee + 255) / 256, 256>>>(ei);
    k_scan1  <<<NB, 256>>>();
    k_scan2  <<<1, 512>>>();
    k_scan3  <<<NB, 256>>>();
    k_scatter<<<(Ee + 255) / 256, 256>>>(ei, eattr, We);

    // join: edge passes need projections too
    cudaStreamWaitEvent(0, g_hx.join, 0);
    k_pass1  <<<(Nn + 7) / 8, 256>>>();
    k_pass2  <<<(Nn + 7) / 8, 256>>>(out);
}

// round 12
// speedup vs baseline: 1.1044x; 1.0048x over previous
#include <cuda_runtime.h>
#include <cstdint>

#define Nn 100000
#define Ee 1600000
#define Hh 8
#define HC 128   // H*C == DIM
#define NB 391   // ceil(Nn/256)

// ---- scratch (device globals; no allocation allowed) ----
__device__ float g_q[(size_t)Nn * HC];
__device__ float g_k[(size_t)Nn * HC];
__device__ float g_v[(size_t)Nn * HC];
__device__ float g_biasS[(size_t)Ee * Hh];   // bias (sorted) -> overwritten with ex in pass 1
__device__ float g_den[(size_t)Nn * Hh];
__device__ int   g_cnt[Nn];
__device__ int   g_off[Nn + 1];
__device__ int   g_pos[Nn];
__device__ int   g_bsum[512];
__device__ int   g_src[Ee];                  // src node, sorted by dst

// ---- host-side fork/join resources (created once; NOT device memory) ----
struct HxStreams {
    cudaStream_t s2;
    cudaEvent_t  fork, join;
    HxStreams() {
        cudaStreamCreateWithFlags(&s2, cudaStreamNonBlocking);
        cudaEventCreateWithFlags(&fork, cudaEventDisableTiming);
        cudaEventCreateWithFlags(&join, cudaEventDisableTiming);
    }
};
static HxStreams g_hx;

// ===========================================================================
// cache-policy helpers (createpolicy + L2::cache_hint — legal on compute_103
// for any access width, unlike the inline .L2::evict_* modifiers)
// ===========================================================================
__device__ __forceinline__ uint64_t pol_last() {
    uint64_t p;
    asm("createpolicy.fractional.L2::evict_last.b64 %0, 1.0;" : "=l"(p));
    return p;
}
__device__ __forceinline__ uint64_t pol_first() {
    uint64_t p;
    asm("createpolicy.fractional.L2::evict_first.b64 %0, 1.0;" : "=l"(p));
    return p;
}
__device__ __forceinline__ float4 ldg_keep4(const float* p, uint64_t pol) {
    float4 v;
    asm volatile("ld.global.nc.L2::cache_hint.v4.f32 {%0,%1,%2,%3}, [%4], %5;"
                 : "=f"(v.x), "=f"(v.y), "=f"(v.z), "=f"(v.w) : "l"(p), "l"(pol));
    return v;
}
__device__ __forceinline__ float ldg_stream(const float* p, uint64_t pol) {
    float v;
    asm volatile("ld.global.nc.L2::cache_hint.f32 %0, [%1], %2;" : "=f"(v) : "l"(p), "l"(pol));
    return v;
}
__device__ __forceinline__ int ldg_stream_i(const int* p, uint64_t pol) {
    int v;
    asm volatile("ld.global.nc.L2::cache_hint.s32 %0, [%1], %2;" : "=r"(v) : "l"(p), "l"(pol));
    return v;
}
__device__ __forceinline__ float4 ldg_stream4(const float* p, uint64_t pol) {
    float4 v;
    asm volatile("ld.global.nc.L2::cache_hint.v4.f32 {%0,%1,%2,%3}, [%4], %5;"
                 : "=f"(v.x), "=f"(v.y), "=f"(v.z), "=f"(v.w) : "l"(p), "l"(pol));
    return v;
}
__device__ __forceinline__ void stg_stream(float* p, float v, uint64_t pol) {
    asm volatile("st.global.L2::cache_hint.f32 [%0], %1, %2;" :: "l"(p), "f"(v), "l"(pol));
}
__device__ __forceinline__ void stg_stream4(float* p, float4 v, uint64_t pol) {
    asm volatile("st.global.L2::cache_hint.v4.f32 [%0], {%1,%2,%3,%4}, %5;"
                 :: "l"(p), "f"(v.x), "f"(v.y), "f"(v.z), "f"(v.w), "l"(pol));
}

// ===========================================================================
// tf32 helpers (base PTX, works on compute_103)
// ===========================================================================
__device__ __forceinline__ float tf32_rna(float f) {
    uint32_t u;
    asm("cvt.rna.tf32.f32 %0, %1;" : "=r"(u) : "f"(f));
    return __uint_as_float(u);
}

__device__ __forceinline__ void mma8(float* d, const uint32_t* a,
                                     uint32_t b0, uint32_t b1) {
    asm volatile(
        "mma.sync.aligned.m16n8k8.row.col.f32.tf32.tf32.f32 "
        "{%0,%1,%2,%3}, {%4,%5,%6,%7}, {%8,%9}, {%0,%1,%2,%3};"
        : "+f"(d[0]), "+f"(d[1]), "+f"(d[2]), "+f"(d[3])
        : "r"(a[0]), "r"(a[1]), "r"(a[2]), "r"(a[3]), "r"(b0), "r"(b1));
}

// ===========================================================================
// projections via tensor cores (3xTF32): q/k/v = x @ W.T
// ===========================================================================
#define KC   32
#define PAD  36
#define SM_FLOATS (4 * 128 * PAD)

__global__ __launch_bounds__(256, 2) void k_projMMA(
    const float* __restrict__ x,
    const float* __restrict__ Wq,
    const float* __restrict__ Wk,
    const float* __restrict__ Wv)
{
    extern __shared__ float sm[];
    float* AsH = sm;
    float* AsL = AsH + 128 * PAD;
    float* BsH = AsL + 128 * PAD;
    float* BsL = BsH + 128 * PAD;

    const int tid   = threadIdx.x;
    const int wid   = tid >> 5;
    const int lane  = tid & 31;
    const int warpM = wid & 3;
    const int warpN = wid >> 2;
    const int gr    = lane >> 2;
    const int qt    = lane & 3;
    const int row0  = blockIdx.x * 128;

    const float* W  = (blockIdx.y == 0) ? Wq : (blockIdx.y == 1) ? Wk : Wv;
    float*  outp    = (blockIdx.y == 0) ? g_q : (blockIdx.y == 1) ? g_k : g_v;

    float d[2][8][4];
#pragma unroll
    for (int mf = 0; mf < 2; mf++)
#pragma unroll
        for (int nf = 0; nf < 8; nf++)
#pragma unroll
            for (int i = 0; i < 4; i++) d[mf][nf][i] = 0.f;

#pragma unroll 1
    for (int kc = 0; kc < 128; kc += KC) {
#pragma unroll
        for (int it = 0; it < 4; it++) {
            int lin = tid + it * 256;
            int r   = lin >> 3;
            int c4  = (lin & 7) << 2;
            float4 v = make_float4(0.f, 0.f, 0.f, 0.f);
            if (row0 + r < Nn)
                v = *(const float4*)(x + (size_t)(row0 + r) * 128 + kc + c4);
            float4 hi = make_float4(tf32_rna(v.x), tf32_rna(v.y), tf32_rna(v.z), tf32_rna(v.w));
            float4 lo = make_float4(tf32_rna(v.x - hi.x), tf32_rna(v.y - hi.y),
                                    tf32_rna(v.z - hi.z), tf32_rna(v.w - hi.w));
            *(float4*)(AsH + r * PAD + c4) = hi;
            *(float4*)(AsL + r * PAD + c4) = lo;

            float4 w = *(const float4*)(W + (size_t)r * 128 + kc + c4);
            float4 wh = make_float4(tf32_rna(w.x), tf32_rna(w.y), tf32_rna(w.z), tf32_rna(w.w));
            float4 wl = make_float4(tf32_rna(w.x - wh.x), tf32_rna(w.y - wh.y),
                                    tf32_rna(w.z - wh.z), tf32_rna(w.w - wh.w));
            *(float4*)(BsH + r * PAD + c4) = wh;
            *(float4*)(BsL + r * PAD + c4) = wl;
        }
        __syncthreads();

#pragma unroll
        for (int k0 = 0; k0 < KC; k0 += 8) {
            uint32_t aH[2][4], aL[2][4];
#pragma unroll
            for (int mf = 0; mf < 2; mf++) {
                const float* pH = AsH + (warpM * 32 + mf * 16 + gr) * PAD + k0 + qt;
                const float* pL = AsL + (warpM * 32 + mf * 16 + gr) * PAD + k0 + qt;
                aH[mf][0] = __float_as_uint(pH[0]);
                aH[mf][1] = __float_as_uint(pH[8 * PAD]);
                aH[mf][2] = __float_as_uint(pH[4]);
                aH[mf][3] = __float_as_uint(pH[8 * PAD + 4]);
                aL[mf][0] = __float_as_uint(pL[0]);
                aL[mf][1] = __float_as_uint(pL[8 * PAD]);
                aL[mf][2] = __float_as_uint(pL[4]);
                aL[mf][3] = __float_as_uint(pL[8 * PAD + 4]);
            }
#pragma unroll
            for (int nf = 0; nf < 8; nf++) {
                const float* pBH = BsH + (warpN * 64 + nf * 8 + gr) * PAD + k0 + qt;
                const float* pBL = BsL + (warpN * 64 + nf * 8 + gr) * PAD + k0 + qt;
                uint32_t bh0 = __float_as_uint(pBH[0]);
                uint32_t bh1 = __float_as_uint(pBH[4]);
                uint32_t bl0 = __float_as_uint(pBL[0]);
                uint32_t bl1 = __float_as_uint(pBL[4]);
                mma8(d[0][nf], aH[0], bh0, bh1);
                mma8(d[1][nf], aH[1], bh0, bh1);
                mma8(d[0][nf], aH[0], bl0, bl1);
                mma8(d[1][nf], aH[1], bl0, bl1);
                mma8(d[0][nf], aL[0], bh0, bh1);
                mma8(d[1][nf], aL[1], bh0, bh1);
            }
        }
        __syncthreads();
    }

#pragma unroll
    for (int mf = 0; mf < 2; mf++) {
        int r = row0 + warpM * 32 + mf * 16 + gr;
#pragma unroll
        for (int nf = 0; nf < 8; nf++) {
            int c = warpN * 64 + nf * 8 + qt * 2;
            if (r < Nn)
                *(float2*)(outp + (size_t)r * 128 + c) = make_float2(d[mf][nf][0], d[mf][nf][1]);
            if (r + 8 < Nn)
                *(float2*)(outp + (size_t)(r + 8) * 128 + c) = make_float2(d[mf][nf][2], d[mf][nf][3]);
        }
    }
}

// ---------------------------------------------------------------------------
__global__ void k_zero() {
    int i = blockIdx.x * 256 + threadIdx.x;
    if (i < Nn) g_cnt[i] = 0;
}

// ---------------------------------------------------------------------------
// counting sort by dst: histogram -> scan -> scatter(+bias)
// ---------------------------------------------------------------------------
__global__ void k_hist(const int* __restrict__ ei) {
    int e = blockIdx.x * 256 + threadIdx.x;
    if (e < Ee) atomicAdd(&g_cnt[ei[Ee + e]], 1);
}

__global__ void k_scan1() {
    __shared__ int sh[256];
    int i = blockIdx.x * 256 + threadIdx.x;
    int v = (i < Nn) ? g_cnt[i] : 0;
    sh[threadIdx.x] = v;
    __syncthreads();
#pragma unroll
    for (int s = 128; s > 0; s >>= 1) {
        if (threadIdx.x < s) sh[threadIdx.x] += sh[threadIdx.x + s];
        __syncthreads();
    }
    if (threadIdx.x == 0) g_bsum[blockIdx.x] = sh[0];
}

__global__ void k_scan2() {
    __shared__ int sh[512];
    int t = threadIdx.x;
    sh[t] = (t < NB) ? g_bsum[t] : 0;
    __syncthreads();
#pragma unroll
    for (int s = 1; s < 512; s <<= 1) {
        int add = (t >= s) ? sh[t - s] : 0;
        __syncthreads();
        sh[t] += add;
        __syncthreads();
    }
    if (t < NB) g_bsum[t] = (t == 0) ? 0 : sh[t - 1];
    if (t == 0) g_off[Nn] = Ee;
}

__global__ void k_scan3() {
    __shared__ int sh[256];
    int i = blockIdx.x * 256 + threadIdx.x;
    int t = threadIdx.x;
    int v = (i < Nn) ? g_cnt[i] : 0;
    sh[t] = v;
    __syncthreads();
#pragma unroll
    for (int s = 1; s < 256; s <<= 1) {
        int add = (t >= s) ? sh[t - s] : 0;
        __syncthreads();
        sh[t] += add;
        __syncthreads();
    }
    if (i < Nn) {
        int off = g_bsum[blockIdx.x] + sh[t] - v;
        g_off[i] = off;
        g_pos[i] = off;
    }
}

// ---------------------------------------------------------------------------
// scatter + edge-bias precompute. eattr staged through smem (coalesced);
// streaming traffic tagged evict_first via cache_hint policy.
// ---------------------------------------------------------------------------
__global__ __launch_bounds__(256) void k_scatter(
    const int* __restrict__ ei,
    const float* __restrict__ eattr,
    const float* __restrict__ We)
{
    __shared__ float We_s[256];
    __shared__ float at[256 * 33];     // 256 edges x 32 attrs, stride 33
    We_s[threadIdx.x] = We[threadIdx.x];

    const uint64_t pf = pol_first();
    const int tid = threadIdx.x;
    const int e0  = blockIdx.x * 256;

    // coalesced load of this block's 256x32 attr slab
    const float* srcp = eattr + (size_t)e0 * 32;
#pragma unroll
    for (int i = 0; i < 8; i++) {
        int f = i * 256 + tid;          // float4 index within slab (0..2047)
        int row = f >> 3;
        int col = (f & 7) << 2;
        if (e0 + row < Ee) {
            float4 v = ldg_stream4(srcp + f * 4, pf);
            float* dst = at + row * 33 + col;
            dst[0] = v.x; dst[1] = v.y; dst[2] = v.z; dst[3] = v.w;
        }
    }
    __syncthreads();

    int e = e0 + tid;
    if (e >= Ee) return;
    int src = ei[e];
    int dst = ei[Ee + e];
    int p = atomicAdd(&g_pos[dst], 1);
    g_src[p] = src;

    float a[32];
    const float* ar = at + tid * 33;
#pragma unroll
    for (int i = 0; i < 32; i++) a[i] = ar[i];

    float b[8];
#pragma unroll
    for (int h = 0; h < 8; h++) {
        const float* w = We_s + h * 32;
        float s = 0.f;
#pragma unroll
        for (int i = 0; i < 32; i++) s = fmaf(a[i], w[i], s);
        b[h] = s;
    }
    float* bp = g_biasS + (size_t)p * 8;
    stg_stream4(bp,     make_float4(b[0], b[1], b[2], b[3]), pf);
    stg_stream4(bp + 4, make_float4(b[4], b[5], b[6], b[7]), pf);
}

// ---------------------------------------------------------------------------
// pass 1: scores. one warp per dst, unroll x4. gathers ONLY k (evict_last);
// bias/src streams evict_first; ex written back evict_first.
// ---------------------------------------------------------------------------
__global__ __launch_bounds__(256) void k_pass1()
{
    const int warp = threadIdx.x >> 5;
    const int lane = threadIdx.x & 31;
    const int d = blockIdx.x * 8 + warp;
    if (d >= Nn) return;

    const uint64_t pl = pol_last();
    const uint64_t pf = pol_first();

    const int beg = g_off[d];
    const int end = g_off[d + 1];
    const int g = lane >> 2, r = lane & 3;

    const float4 q4 = __ldg((const float4*)(g_q + (size_t)d * 128 + lane * 4));

    float den = 0.f;
    int p = beg;
    const int n4 = beg + ((end - beg) & ~3);
#pragma unroll 1
    for (; p < n4; p += 4) {
        int   s[4]; float b[4]; float4 kk[4];
#pragma unroll
        for (int j = 0; j < 4; j++) s[j] = ldg_stream_i(g_src + p + j, pf);
#pragma unroll
        for (int j = 0; j < 4; j++) b[j] = ldg_stream(g_biasS + (size_t)(p + j) * 8 + g, pf);
#pragma unroll
        for (int j = 0; j < 4; j++)
            kk[j] = ldg_keep4(g_k + (size_t)s[j] * 128 + lane * 4, pl);

        float t[4];
#pragma unroll
        for (int j = 0; j < 4; j++)
            t[j] = (q4.x * kk[j].x + q4.y * kk[j].y + q4.z * kk[j].z + q4.w * kk[j].w) * 0.25f;
#pragma unroll
        for (int j = 0; j < 4; j++) {
            t[j] += __shfl_xor_sync(0xffffffffu, t[j], 1);
            t[j] += __shfl_xor_sync(0xffffffffu, t[j], 2);
        }
#pragma unroll
        for (int j = 0; j < 4; j++) {
            float e = __expf(t[j] + b[j]);
            den += e;
            if (r == 0) stg_stream(g_biasS + (size_t)(p + j) * 8 + g, e, pf);
        }
    }
#pragma unroll 1
    for (; p < end; p++) {
        const int s0 = ldg_stream_i(g_src + p, pf);
        const float b0 = ldg_stream(g_biasS + (size_t)p * 8 + g, pf);
        const float4 k0 = ldg_keep4(g_k + (size_t)s0 * 128 + lane * 4, pl);
        float t0 = (q4.x * k0.x + q4.y * k0.y + q4.z * k0.z + q4.w * k0.w) * 0.25f;
        t0 += __shfl_xor_sync(0xffffffffu, t0, 1);
        t0 += __shfl_xor_sync(0xffffffffu, t0, 2);
        const float e0 = __expf(t0 + b0);
        den += e0;
        if (r == 0) stg_stream(g_biasS + (size_t)p * 8 + g, e0, pf);
    }

    if (r == 0) stg_stream(g_den + (size_t)d * 8 + g, den, pf);
}

// ---------------------------------------------------------------------------
// pass 2: aggregate. one warp per dst, unroll x4. gathers ONLY v (evict_last).
// ---------------------------------------------------------------------------
__global__ __launch_bounds__(256) void k_pass2(float* __restrict__ out)
{
    const int warp = threadIdx.x >> 5;
    const int lane = threadIdx.x & 31;
    const int d = blockIdx.x * 8 + warp;
    if (d >= Nn) return;

    const uint64_t pl = pol_last();
    const uint64_t pf = pol_first();

    const int beg = g_off[d];
    const int end = g_off[d + 1];
    const int g = lane >> 2;

    float4 acc = make_float4(0.f, 0.f, 0.f, 0.f);

    int p = beg;
    const int n4 = beg + ((end - beg) & ~3);
#pragma unroll 1
    for (; p < n4; p += 4) {
        int s[4]; float e[4]; float4 vv[4];
#pragma unroll
        for (int j = 0; j < 4; j++) s[j] = ldg_stream_i(g_src + p + j, pf);
#pragma unroll
        for (int j = 0; j < 4; j++) e[j] = ldg_stream(g_biasS + (size_t)(p + j) * 8 + g, pf);
#pragma unroll
        for (int j = 0; j < 4; j++)
            vv[j] = ldg_keep4(g_v + (size_t)s[j] * 128 + lane * 4, pl);
#pragma unroll
        for (int j = 0; j < 4; j++) {
            acc.x = fmaf(e[j], vv[j].x, acc.x);
            acc.y = fmaf(e[j], vv[j].y, acc.y);
            acc.z = fmaf(e[j], vv[j].z, acc.z);
            acc.w = fmaf(e[j], vv[j].w, acc.w);
        }
    }
#pragma unroll 1
    for (; p < end; p++) {
        const int s0 = ldg_stream_i(g_src + p, pf);
        const float e0 = ldg_stream(g_biasS + (size_t)p * 8 + g, pf);
        const float4 v0 = ldg_keep4(g_v + (size_t)s0 * 128 + lane * 4, pl);
        acc.x = fmaf(e0, v0.x, acc.x);
        acc.y = fmaf(e0, v0.y, acc.y);
        acc.z = fmaf(e0, v0.z, acc.z);
        acc.w = fmaf(e0, v0.w, acc.w);
    }

    const float den = ldg_stream(g_den + (size_t)d * 8 + g, pf);
    const float inv = (den > 0.f) ? (1.f / den) : 0.f;
    stg_stream4(out + (size_t)d * 128 + lane * 4,
                make_float4(acc.x * inv, acc.y * inv, acc.z * inv, acc.w * inv), pf);
}

// ---------------------------------------------------------------------------
extern "C" void kernel_launch(void* const* d_in, const int* in_sizes, int n_in,
                              void* d_out, int out_size) {
    const float* x     = (const float*)d_in[0];
    const int*   ei    = (const int*)  d_in[1];
    const float* eattr = (const float*)d_in[2];
    const float* Wq    = (const float*)d_in[3];
    const float* Wk    = (const float*)d_in[4];
    const float* Wv    = (const float*)d_in[5];
    const float* We    = (const float*)d_in[6];
    float* out = (float*)d_out;

    cudaFuncSetAttribute(k_projMMA, cudaFuncAttributeMaxDynamicSharedMemorySize,
                         SM_FLOATS * (int)sizeof(float));

    // fork: projection on side stream
    cudaEventRecord(g_hx.fork, 0);
    cudaStreamWaitEvent(g_hx.s2, g_hx.fork, 0);
    dim3 pg((Nn + 127) / 128, 3);
    k_projMMA<<<pg, 256, SM_FLOATS * sizeof(float), g_hx.s2>>>(x, Wq, Wk, Wv);
    cudaEventRecord(g_hx.join, g_hx.s2);

    // edge-sort chain on main stream
    k_zero   <<<NB, 256>>>();
    k_hist   <<<(Ee + 255) / 256, 256>>>(ei);
    k_scan1  <<<NB, 256>>>();
    k_scan2  <<<1, 512>>>();
    k_scan3  <<<NB, 256>>>();
    k_scatter<<<(Ee + 255) / 256, 256>>>(ei, eattr, We);

    // join: edge passes need projections too
    cudaStreamWaitEvent(0, g_hx.join, 0);
    k_pass1  <<<(Nn + 7) / 8, 256>>>();
    k_pass2  <<<(Nn + 7) / 8, 256>>>(out);
}